// round 5
// baseline (speedup 1.0000x reference)
#include <cuda_runtime.h>
#include <cstdint>
#include <math_constants.h>

#define ENC_DIM 512
#define DEC_DIM 1024
#define HID     128
#define BB      64
#define TT      2048

// ---------------- scratch (no cudaMalloc allowed) ----------------
__device__ float g_q[BB * HID];
__device__ float g_scores[BB * TT];
__device__ float g_ctx_part[16][BB][ENC_DIM];
__device__ int   g_mask_u8;

// ---------------- helpers ----------------
__device__ __forceinline__ uint32_t smem_u32(const void* p) {
    uint32_t a;
    asm("{ .reg .u64 t; cvta.to.shared.u64 t, %1; cvt.u32.u64 %0, t; }" : "=r"(a) : "l"(p));
    return a;
}
__device__ __forceinline__ void cp_async16(uint32_t dst, const void* src) {
    asm volatile("cp.async.cg.shared.global [%0], [%1], 16;" :: "r"(dst), "l"(src));
}
#define CP_COMMIT()  asm volatile("cp.async.commit_group;" ::: "memory")
#define CP_WAIT(n)   asm volatile("cp.async.wait_group %0;" :: "n"(n) : "memory")

// ---------------- kernel 0: detect mask dtype ----------------
__global__ void detect_mask_kernel(const uint4* __restrict__ m) {
    __shared__ int s;
    if (threadIdx.x == 0) s = 0;
    __syncthreads();
    int found = 0;
    const int n16 = (BB * TT) / 16;
    for (int i = threadIdx.x; i < n16; i += blockDim.x) {
        uint4 v = m[i];
        found |= (v.x > 1u) | (v.y > 1u) | (v.z > 1u) | (v.w > 1u);
    }
    if (found) atomicOr(&s, 1);
    __syncthreads();
    if (threadIdx.x == 0) g_mask_u8 = s;
}

// ---------------- kernel 1: q projection ----------------
__global__ void q_kernel(const float* __restrict__ dec, const float* __restrict__ Ww) {
    __shared__ float sdec[DEC_DIM];
    int b = blockIdx.x;
    for (int i = threadIdx.x; i < DEC_DIM; i += blockDim.x)
        sdec[i] = dec[b * DEC_DIM + i];
    __syncthreads();
    int h = threadIdx.x;
    const float4* wr = (const float4*)(Ww + (size_t)h * DEC_DIM);
    const float4* dr = (const float4*)sdec;
    float acc = 0.f;
#pragma unroll 8
    for (int i = 0; i < DEC_DIM / 4; i++) {
        float4 w4 = wr[i];
        float4 d4 = dr[i];
        acc += w4.x * d4.x + w4.y * d4.y + w4.z * d4.z + w4.w * d4.w;
    }
    g_q[b * HID + h] = acc;
}

// ---------------- kernel 2: scores via mma.sync tf32, cp.async pipelined ----------------
// Block tile 128 tokens x 128 hid, KC=32, 2-stage cp.async double buffer.
// 8 warps in 4(M) x 2(N); warp tile 32x64 = 2 m16 x 8 n8 per k8 step.
// fp32 bits fed directly to tf32 MMA (HW truncation; see error model).
#define KC       32
#define PITCH_A  36
#define TILE_W   (128 * PITCH_A)             // words per As/Bs tile
#define STAGE_W  (2 * TILE_W)                // As + Bs
#define NCHUNK   (ENC_DIM / KC)              // 16
#define DYN_W    (2 * STAGE_W)               // 2 stages
#define DYN_BYTES (DYN_W * 4)

__global__ __launch_bounds__(256, 2) void scores_kernel(
    const float* __restrict__ enc, const float* __restrict__ Vw,
    const float* __restrict__ Vb, const float* __restrict__ ww,
    const float* __restrict__ wb)
{
    extern __shared__ unsigned dsm[];
    __shared__ float sVb[HID], sq[HID], sw[HID];
    __shared__ float srow[128];

    int bidx = blockIdx.x;         // 0..1023
    int b    = bidx >> 4;
    int t0   = (bidx & 15) << 7;

    int tid    = threadIdx.x;
    int lane   = tid & 31;
    int wid    = tid >> 5;
    int warp_m = wid >> 1;         // 0..3
    int warp_n = wid & 1;          // 0..1
    int g      = lane >> 2;        // 0..7
    int tig    = lane & 3;         // 0..3

    if (tid < HID) {
        sVb[tid]  = Vb[tid];
        sq[tid]   = g_q[b * HID + tid];
        sw[tid]   = ww[tid];
        srow[tid] = 0.f;
    }

    const float* Ag = enc + ((size_t)(b * TT + t0)) * ENC_DIM;
    uint32_t dyn_addr = smem_u32(dsm);

    // per-thread load slots: 4 A rows + 4 B rows per chunk (16B each)
    int lrow = tid >> 1;              // 0..127
    int lk4  = (tid & 1) << 2;        // 0 or 4 (float index of 16B unit *4)

    auto load_chunk = [&](int c) {
        int st = c & 1;
        uint32_t sbA = dyn_addr + (st * STAGE_W) * 4;
        uint32_t sbB = sbA + TILE_W * 4;
        int kc = c * KC;
#pragma unroll
        for (int i = 0; i < 2; i++) {
            int row = lrow;           // reuse same row, two 16B units apart
            int k4  = lk4 + i * 8;    // 0,8 or 4,12  (floats)
            cp_async16(sbA + (row * PITCH_A + k4) * 4,
                       Ag + (size_t)row * ENC_DIM + kc + k4);
            cp_async16(sbB + (row * PITCH_A + k4) * 4,
                       Vw + (size_t)row * ENC_DIM + kc + k4);
        }
#pragma unroll
        for (int i = 0; i < 2; i++) {
            int row = lrow;
            int k4  = lk4 + i * 8 + 16;
            cp_async16(sbA + (row * PITCH_A + k4) * 4,
                       Ag + (size_t)row * ENC_DIM + kc + k4);
            cp_async16(sbB + (row * PITCH_A + k4) * 4,
                       Vw + (size_t)row * ENC_DIM + kc + k4);
        }
        CP_COMMIT();
    };

    float c_[2][8][4];
#pragma unroll
    for (int mt = 0; mt < 2; mt++)
#pragma unroll
        for (int nt = 0; nt < 8; nt++)
#pragma unroll
            for (int r = 0; r < 4; r++) c_[mt][nt][r] = 0.f;

    load_chunk(0);

    for (int c = 0; c < NCHUNK; c++) {
        if (c + 1 < NCHUNK) load_chunk(c + 1);
        if (c + 1 < NCHUNK) CP_WAIT(1); else CP_WAIT(0);
        __syncthreads();

        const unsigned* As = dsm + (c & 1) * STAGE_W;
        const unsigned* Bs = As + TILE_W;

#pragma unroll
        for (int ks = 0; ks < KC / 8; ks++) {
            int k0 = ks * 8;
            unsigned a[2][4];
#pragma unroll
            for (int mt = 0; mt < 2; mt++) {
                int r0 = warp_m * 32 + mt * 16 + g;
                a[mt][0] = As[r0 * PITCH_A + k0 + tig];
                a[mt][1] = As[(r0 + 8) * PITCH_A + k0 + tig];
                a[mt][2] = As[r0 * PITCH_A + k0 + tig + 4];
                a[mt][3] = As[(r0 + 8) * PITCH_A + k0 + tig + 4];
            }
#pragma unroll
            for (int nt = 0; nt < 8; nt++) {
                int n0 = warp_n * 64 + nt * 8;
                unsigned b0 = Bs[(n0 + g) * PITCH_A + k0 + tig];
                unsigned b1 = Bs[(n0 + g) * PITCH_A + k0 + tig + 4];
#pragma unroll
                for (int mt = 0; mt < 2; mt++) {
                    asm volatile(
                        "mma.sync.aligned.m16n8k8.row.col.f32.tf32.tf32.f32 "
                        "{%0,%1,%2,%3}, {%4,%5,%6,%7}, {%8,%9}, {%0,%1,%2,%3};"
                        : "+f"(c_[mt][nt][0]), "+f"(c_[mt][nt][1]),
                          "+f"(c_[mt][nt][2]), "+f"(c_[mt][nt][3])
                        : "r"(a[mt][0]), "r"(a[mt][1]), "r"(a[mt][2]), "r"(a[mt][3]),
                          "r"(b0), "r"(b1));
                }
            }
        }
        __syncthreads();   // stage c&1 fully consumed before load(c+2) overwrites it
    }

    // epilogue: score[t] = sum_c tanh(k + Vb + q) * w  (+wb at store)
#pragma unroll
    for (int mt = 0; mt < 2; mt++) {
#pragma unroll
        for (int rr = 0; rr < 2; rr++) {
            int row = warp_m * 32 + mt * 16 + rr * 8 + g;
            float partial = 0.f;
#pragma unroll
            for (int nt = 0; nt < 8; nt++) {
                int c0 = warp_n * 64 + nt * 8 + 2 * tig;
                float v0 = c_[mt][nt][2 * rr]     + sVb[c0]     + sq[c0];
                float v1 = c_[mt][nt][2 * rr + 1] + sVb[c0 + 1] + sq[c0 + 1];
                partial += tanhf(v0) * sw[c0] + tanhf(v1) * sw[c0 + 1];
            }
            partial += __shfl_xor_sync(0xffffffffu, partial, 1);
            partial += __shfl_xor_sync(0xffffffffu, partial, 2);
            if (tig == 0) atomicAdd(&srow[row], partial);
        }
    }
    __syncthreads();
    if (tid < 128)
        g_scores[b * TT + t0 + tid] = srow[tid] + wb[0];
}

// ---------------- kernel 3: masked softmax per batch row ----------------
__global__ void softmax_kernel(const unsigned char* __restrict__ mask,
                               float* __restrict__ out_w) {
    int b   = blockIdx.x;
    int tid = threadIdx.x;          // 256 threads
    int lane = tid & 31, wid = tid >> 5;
    bool u8 = (g_mask_u8 != 0);
    __shared__ float redm[8];
    __shared__ float reds[8];
    __shared__ float bc[2];

    float vals[8];
    float mx = -CUDART_INF_F;
#pragma unroll
    for (int i = 0; i < 8; i++) {
        int t = tid + i * 256;
        float s = g_scores[b * TT + t];
        unsigned char m = u8 ? mask[b * TT + t] : mask[4 * (size_t)(b * TT + t)];
        if (m) s = -CUDART_INF_F;
        vals[i] = s;
        mx = fmaxf(mx, s);
    }
#pragma unroll
    for (int off = 16; off; off >>= 1)
        mx = fmaxf(mx, __shfl_xor_sync(0xffffffffu, mx, off));
    if (lane == 0) redm[wid] = mx;
    __syncthreads();
    if (tid == 0) {
        float m = redm[0];
#pragma unroll
        for (int w = 1; w < 8; w++) m = fmaxf(m, redm[w]);
        bc[0] = m;
    }
    __syncthreads();
    mx = bc[0];

    float sum = 0.f;
#pragma unroll
    for (int i = 0; i < 8; i++) {
        vals[i] = __expf(vals[i] - mx);
        sum += vals[i];
    }
#pragma unroll
    for (int off = 16; off; off >>= 1)
        sum += __shfl_xor_sync(0xffffffffu, sum, off);
    if (lane == 0) reds[wid] = sum;
    __syncthreads();
    if (tid == 0) {
        float s = 0.f;
#pragma unroll
        for (int w = 0; w < 8; w++) s += reds[w];
        bc[1] = 1.f / s;
    }
    __syncthreads();
    float inv = bc[1];
#pragma unroll
    for (int i = 0; i < 8; i++)
        out_w[b * TT + tid + i * 256] = vals[i] * inv;
}

// ---------------- kernel 4: context partials ----------------
__global__ void ctx_partial_kernel(const float* __restrict__ enc,
                                   const float* __restrict__ weights) {
    int seg = blockIdx.x;   // 0..15
    int b   = blockIdx.y;
    int tid = threadIdx.x;  // 128
    __shared__ float ws[128];
    int tbase = seg * 128;
    ws[tid] = weights[b * TT + tbase + tid];
    __syncthreads();

    float4 acc = make_float4(0.f, 0.f, 0.f, 0.f);
    const float4* ep = (const float4*)(enc + ((size_t)b * TT + tbase) * ENC_DIM) + tid;
#pragma unroll 8
    for (int t = 0; t < 128; t++) {
        float4 v = ep[(size_t)t * (ENC_DIM / 4)];
        float w  = ws[t];
        acc.x += v.x * w; acc.y += v.y * w; acc.z += v.z * w; acc.w += v.w * w;
    }
    ((float4*)g_ctx_part)[((size_t)seg * BB + b) * (ENC_DIM / 4) + tid] = acc;
}

__global__ void ctx_combine_kernel(float* __restrict__ out_ctx) {
    int i = blockIdx.x * blockDim.x + threadIdx.x;
    int b = i >> 9, e = i & 511;
    float s = 0.f;
#pragma unroll
    for (int seg = 0; seg < 16; seg++) s += g_ctx_part[seg][b][e];
    out_ctx[i] = s;
}

// ---------------- launch ----------------
extern "C" void kernel_launch(void* const* d_in, const int* in_sizes, int n_in,
                              void* d_out, int out_size) {
    const float*         enc  = (const float*)d_in[0];
    const float*         dec  = (const float*)d_in[1];
    const unsigned char* mask = (const unsigned char*)d_in[2];
    const float*         Vw   = (const float*)d_in[3];
    const float*         Vb   = (const float*)d_in[4];
    const float*         Ww   = (const float*)d_in[5];
    const float*         ww   = (const float*)d_in[6];
    const float*         wb   = (const float*)d_in[7];

    float* out_ctx = (float*)d_out;                    // [B, ENC_DIM]
    float* out_w   = (float*)d_out + BB * ENC_DIM;     // [B, T]

    static int attr_done = 0;
    if (!attr_done) {
        cudaFuncSetAttribute(scores_kernel,
                             cudaFuncAttributeMaxDynamicSharedMemorySize, DYN_BYTES);
        attr_done = 1;
    }

    detect_mask_kernel<<<1, 1024>>>((const uint4*)mask);
    q_kernel<<<BB, HID>>>(dec, Ww);
    scores_kernel<<<1024, 256, DYN_BYTES>>>(enc, Vw, Vb, ww, wb);
    softmax_kernel<<<BB, 256>>>(mask, out_w);
    ctx_partial_kernel<<<dim3(16, BB), 128>>>(enc, out_w);
    ctx_combine_kernel<<<(BB * ENC_DIM) / 256, 256>>>(out_ctx);
}

// round 6
// speedup vs baseline: 1.2340x; 1.2340x over previous
#include <cuda_runtime.h>
#include <cuda_fp16.h>
#include <cstdint>
#include <math_constants.h>

#define ENC_DIM 512
#define DEC_DIM 1024
#define HID     128
#define BB      64
#define TT      2048

// ---------------- scratch (no cudaMalloc allowed) ----------------
__device__ float g_q[BB * HID];
__device__ float g_scores[BB * TT];
__device__ float g_ctx_part[16][BB][ENC_DIM];
__device__ int   g_mask_u8;

// ---------------- kernel 0: detect mask dtype ----------------
__global__ void detect_mask_kernel(const uint4* __restrict__ m) {
    __shared__ int s;
    if (threadIdx.x == 0) s = 0;
    __syncthreads();
    int found = 0;
    const int n16 = (BB * TT) / 16;
    for (int i = threadIdx.x; i < n16; i += blockDim.x) {
        uint4 v = m[i];
        found |= (v.x > 1u) | (v.y > 1u) | (v.z > 1u) | (v.w > 1u);
    }
    if (found) atomicOr(&s, 1);
    __syncthreads();
    if (threadIdx.x == 0) g_mask_u8 = s;
}

// ---------------- kernel 1: q projection ----------------
__global__ void q_kernel(const float* __restrict__ dec, const float* __restrict__ Ww) {
    __shared__ float sdec[DEC_DIM];
    int b = blockIdx.x;
    for (int i = threadIdx.x; i < DEC_DIM; i += blockDim.x)
        sdec[i] = dec[b * DEC_DIM + i];
    __syncthreads();
    int h = threadIdx.x;
    const float4* wr = (const float4*)(Ww + (size_t)h * DEC_DIM);
    const float4* dr = (const float4*)sdec;
    float acc = 0.f;
#pragma unroll 8
    for (int i = 0; i < DEC_DIM / 4; i++) {
        float4 w4 = wr[i];
        float4 d4 = dr[i];
        acc += w4.x * d4.x + w4.y * d4.y + w4.z * d4.z + w4.w * d4.w;
    }
    g_q[b * HID + h] = acc;
}

// ---------------- kernel 2: scores via fp16 mma.sync m16n8k16 ----------------
// Block tile 128 tokens x 128 hid. KC=64 (8 chunks). fp32->fp16 rn conversion
// fused into the loader; smem tiles fp16, PITCH_W=36 words/row (72 halves) ->
// fragment LDS banks {36g+tig} mod 32 all distinct (conflict-free).
// 8 warps in 4(M) x 2(N); warp tile 32x64 = 2 m16 x 8 n8 per k16 step.
#define KC      64
#define PITCH_W 36
#define NCHUNK  (ENC_DIM / KC)   // 8

__global__ __launch_bounds__(256, 2) void scores_kernel(
    const float* __restrict__ enc, const float* __restrict__ Vw,
    const float* __restrict__ Vb, const float* __restrict__ ww,
    const float* __restrict__ wb)
{
    __shared__ unsigned As[128 * PITCH_W];   // [token][k halves/2]
    __shared__ unsigned Bs[128 * PITCH_W];   // [hid][k halves/2]
    __shared__ float sVb[HID], sq[HID], sw[HID];
    __shared__ float srow[128];

    int bidx = blockIdx.x;         // 0..1023
    int b    = bidx >> 4;
    int t0   = (bidx & 15) << 7;

    int tid    = threadIdx.x;
    int lane   = tid & 31;
    int wid    = tid >> 5;
    int warp_m = wid >> 1;         // 0..3
    int warp_n = wid & 1;          // 0..1
    int g      = lane >> 2;        // 0..7
    int tig    = lane & 3;         // 0..3

    if (tid < HID) {
        sVb[tid]  = Vb[tid];
        sq[tid]   = g_q[b * HID + tid];
        sw[tid]   = ww[tid];
        srow[tid] = 0.f;
    }

    const float* Ag = enc + ((size_t)(b * TT + t0)) * ENC_DIM;

    float c_[2][8][4];
#pragma unroll
    for (int mt = 0; mt < 2; mt++)
#pragma unroll
        for (int nt = 0; nt < 8; nt++)
#pragma unroll
            for (int r = 0; r < 4; r++) c_[mt][nt][r] = 0.f;

    for (int kc = 0; kc < ENC_DIM; kc += KC) {
        __syncthreads();  // previous chunk fully consumed
        // load + convert: 128 rows x 64 floats per matrix.
        // warp instruction = 2 rows x 16 float4 = 2 x 256B contiguous gmem.
#pragma unroll
        for (int i = 0; i < 8; i++) {
            int idx = tid + i * 256;          // 0..2047
            int row = idx >> 4;
            int k4  = (idx & 15) << 2;        // 0..60
            float4 v = *(const float4*)(Ag + (size_t)row * ENC_DIM + kc + k4);
            __half2 h0 = __floats2half2_rn(v.x, v.y);
            __half2 h1 = __floats2half2_rn(v.z, v.w);
            uint2 u;
            u.x = *(unsigned*)&h0;
            u.y = *(unsigned*)&h1;
            *(uint2*)&As[row * PITCH_W + (k4 >> 1)] = u;
        }
#pragma unroll
        for (int i = 0; i < 8; i++) {
            int idx = tid + i * 256;
            int row = idx >> 4;
            int k4  = (idx & 15) << 2;
            float4 v = *(const float4*)(Vw + (size_t)row * ENC_DIM + kc + k4);
            __half2 h0 = __floats2half2_rn(v.x, v.y);
            __half2 h1 = __floats2half2_rn(v.z, v.w);
            uint2 u;
            u.x = *(unsigned*)&h0;
            u.y = *(unsigned*)&h1;
            *(uint2*)&Bs[row * PITCH_W + (k4 >> 1)] = u;
        }
        __syncthreads();

#pragma unroll
        for (int ks = 0; ks < KC / 16; ks++) {
            int k0w = ks * 8;   // word offset of this k16 step
            // A fragments: a0={A[g][2tig],+1} a1={A[g+8][..]} a2,a3 at k+8
            unsigned a[2][4];
#pragma unroll
            for (int mt = 0; mt < 2; mt++) {
                int r0 = warp_m * 32 + mt * 16 + g;
                a[mt][0] = As[r0 * PITCH_W + k0w + tig];
                a[mt][1] = As[(r0 + 8) * PITCH_W + k0w + tig];
                a[mt][2] = As[r0 * PITCH_W + k0w + tig + 4];
                a[mt][3] = As[(r0 + 8) * PITCH_W + k0w + tig + 4];
            }
#pragma unroll
            for (int nt = 0; nt < 8; nt++) {
                int n0 = warp_n * 64 + nt * 8 + g;
                unsigned b0 = Bs[n0 * PITCH_W + k0w + tig];
                unsigned b1 = Bs[n0 * PITCH_W + k0w + tig + 4];
#pragma unroll
                for (int mt = 0; mt < 2; mt++) {
                    asm volatile(
                        "mma.sync.aligned.m16n8k16.row.col.f32.f16.f16.f32 "
                        "{%0,%1,%2,%3}, {%4,%5,%6,%7}, {%8,%9}, {%0,%1,%2,%3};"
                        : "+f"(c_[mt][nt][0]), "+f"(c_[mt][nt][1]),
                          "+f"(c_[mt][nt][2]), "+f"(c_[mt][nt][3])
                        : "r"(a[mt][0]), "r"(a[mt][1]), "r"(a[mt][2]), "r"(a[mt][3]),
                          "r"(b0), "r"(b1));
                }
            }
        }
    }

    // epilogue: score[t] = sum_c tanh(k + Vb + q) * w  (+wb at store)
#pragma unroll
    for (int mt = 0; mt < 2; mt++) {
#pragma unroll
        for (int rr = 0; rr < 2; rr++) {
            int row = warp_m * 32 + mt * 16 + rr * 8 + g;
            float partial = 0.f;
#pragma unroll
            for (int nt = 0; nt < 8; nt++) {
                int c0 = warp_n * 64 + nt * 8 + 2 * tig;
                float v0 = c_[mt][nt][2 * rr]     + sVb[c0]     + sq[c0];
                float v1 = c_[mt][nt][2 * rr + 1] + sVb[c0 + 1] + sq[c0 + 1];
                partial += tanhf(v0) * sw[c0] + tanhf(v1) * sw[c0 + 1];
            }
            partial += __shfl_xor_sync(0xffffffffu, partial, 1);
            partial += __shfl_xor_sync(0xffffffffu, partial, 2);
            if (tig == 0) atomicAdd(&srow[row], partial);
        }
    }
    __syncthreads();
    if (tid < 128)
        g_scores[b * TT + t0 + tid] = srow[tid] + wb[0];
}

// ---------------- kernel 3: masked softmax per batch row ----------------
__global__ void softmax_kernel(const unsigned char* __restrict__ mask,
                               float* __restrict__ out_w) {
    int b   = blockIdx.x;
    int tid = threadIdx.x;          // 256 threads
    int lane = tid & 31, wid = tid >> 5;
    bool u8 = (g_mask_u8 != 0);
    __shared__ float redm[8];
    __shared__ float reds[8];
    __shared__ float bc[2];

    float vals[8];
    float mx = -CUDART_INF_F;
#pragma unroll
    for (int i = 0; i < 8; i++) {
        int t = tid + i * 256;
        float s = g_scores[b * TT + t];
        unsigned char m = u8 ? mask[b * TT + t] : mask[4 * (size_t)(b * TT + t)];
        if (m) s = -CUDART_INF_F;
        vals[i] = s;
        mx = fmaxf(mx, s);
    }
#pragma unroll
    for (int off = 16; off; off >>= 1)
        mx = fmaxf(mx, __shfl_xor_sync(0xffffffffu, mx, off));
    if (lane == 0) redm[wid] = mx;
    __syncthreads();
    if (tid == 0) {
        float m = redm[0];
#pragma unroll
        for (int w = 1; w < 8; w++) m = fmaxf(m, redm[w]);
        bc[0] = m;
    }
    __syncthreads();
    mx = bc[0];

    float sum = 0.f;
#pragma unroll
    for (int i = 0; i < 8; i++) {
        vals[i] = __expf(vals[i] - mx);
        sum += vals[i];
    }
#pragma unroll
    for (int off = 16; off; off >>= 1)
        sum += __shfl_xor_sync(0xffffffffu, sum, off);
    if (lane == 0) reds[wid] = sum;
    __syncthreads();
    if (tid == 0) {
        float s = 0.f;
#pragma unroll
        for (int w = 0; w < 8; w++) s += reds[w];
        bc[1] = 1.f / s;
    }
    __syncthreads();
    float inv = bc[1];
#pragma unroll
    for (int i = 0; i < 8; i++)
        out_w[b * TT + tid + i * 256] = vals[i] * inv;
}

// ---------------- kernel 4: context partials (t split 16-way) ----------------
__global__ void ctx_partial_kernel(const float* __restrict__ enc,
                                   const float* __restrict__ weights) {
    int seg = blockIdx.x;   // 0..15
    int b   = blockIdx.y;
    int tid = threadIdx.x;  // 128
    __shared__ float ws[128];
    int tbase = seg * 128;
    ws[tid] = weights[b * TT + tbase + tid];
    __syncthreads();

    float4 acc = make_float4(0.f, 0.f, 0.f, 0.f);
    const float4* ep = (const float4*)(enc + ((size_t)b * TT + tbase) * ENC_DIM) + tid;
#pragma unroll 8
    for (int t = 0; t < 128; t++) {
        float4 v = ep[(size_t)t * (ENC_DIM / 4)];
        float w  = ws[t];
        acc.x += v.x * w; acc.y += v.y * w; acc.z += v.z * w; acc.w += v.w * w;
    }
    ((float4*)g_ctx_part)[((size_t)seg * BB + b) * (ENC_DIM / 4) + tid] = acc;
}

__global__ void ctx_combine_kernel(float* __restrict__ out_ctx) {
    int i = blockIdx.x * blockDim.x + threadIdx.x;
    int b = i >> 9, e = i & 511;
    float s = 0.f;
#pragma unroll
    for (int seg = 0; seg < 16; seg++) s += g_ctx_part[seg][b][e];
    out_ctx[i] = s;
}

// ---------------- launch ----------------
extern "C" void kernel_launch(void* const* d_in, const int* in_sizes, int n_in,
                              void* d_out, int out_size) {
    const float*         enc  = (const float*)d_in[0];
    const float*         dec  = (const float*)d_in[1];
    const unsigned char* mask = (const unsigned char*)d_in[2];
    const float*         Vw   = (const float*)d_in[3];
    const float*         Vb   = (const float*)d_in[4];
    const float*         Ww   = (const float*)d_in[5];
    const float*         ww   = (const float*)d_in[6];
    const float*         wb   = (const float*)d_in[7];

    float* out_ctx = (float*)d_out;                    // [B, ENC_DIM]
    float* out_w   = (float*)d_out + BB * ENC_DIM;     // [B, T]

    detect_mask_kernel<<<1, 1024>>>((const uint4*)mask);
    q_kernel<<<BB, HID>>>(dec, Ww);
    scores_kernel<<<1024, 256>>>(enc, Vw, Vb, ww, wb);
    softmax_kernel<<<BB, 256>>>(mask, out_w);
    ctx_partial_kernel<<<dim3(16, BB), 128>>>(enc, out_w);
    ctx_combine_kernel<<<(BB * ENC_DIM) / 256, 256>>>(out_ctx);
}

// round 7
// speedup vs baseline: 1.2383x; 1.0035x over previous
#include <cuda_runtime.h>
#include <cstdint>
#include <math_constants.h>

#define ENC_DIM 512
#define DEC_DIM 1024
#define HID     128
#define BB      64
#define TT      2048

// ---------------- scratch (no cudaMalloc allowed) ----------------
__device__ float g_q[BB * HID];
__device__ float g_scores[BB * TT];
__device__ float g_ctx_part[16][BB][ENC_DIM];
__device__ int   g_mask_u8;

// ---------------- helpers ----------------
__device__ __forceinline__ uint32_t smem_u32(const void* p) {
    uint32_t a;
    asm("{ .reg .u64 t; cvta.to.shared.u64 t, %1; cvt.u32.u64 %0, t; }" : "=r"(a) : "l"(p));
    return a;
}
__device__ __forceinline__ void cp_async16(uint32_t dst, const void* src) {
    asm volatile("cp.async.cg.shared.global [%0], [%1], 16;" :: "r"(dst), "l"(src));
}
#define CP_COMMIT()  asm volatile("cp.async.commit_group;" ::: "memory")
#define CP_WAIT(n)   asm volatile("cp.async.wait_group %0;" :: "n"(n) : "memory")

// ---------------- kernel 0: detect mask dtype ----------------
__global__ void detect_mask_kernel(const uint4* __restrict__ m) {
    __shared__ int s;
    if (threadIdx.x == 0) s = 0;
    __syncthreads();
    int found = 0;
    const int n16 = (BB * TT) / 16;
    for (int i = threadIdx.x; i < n16; i += blockDim.x) {
        uint4 v = m[i];
        found |= (v.x > 1u) | (v.y > 1u) | (v.z > 1u) | (v.w > 1u);
    }
    if (found) atomicOr(&s, 1);
    __syncthreads();
    if (threadIdx.x == 0) g_mask_u8 = s;
}

// ---------------- kernel 1: q projection ----------------
__global__ void q_kernel(const float* __restrict__ dec, const float* __restrict__ Ww) {
    __shared__ float sdec[DEC_DIM];
    int b = blockIdx.x;
    for (int i = threadIdx.x; i < DEC_DIM; i += blockDim.x)
        sdec[i] = dec[b * DEC_DIM + i];
    __syncthreads();
    int h = threadIdx.x;
    const float4* wr = (const float4*)(Ww + (size_t)h * DEC_DIM);
    const float4* dr = (const float4*)sdec;
    float acc = 0.f;
#pragma unroll 8
    for (int i = 0; i < DEC_DIM / 4; i++) {
        float4 w4 = wr[i];
        float4 d4 = dr[i];
        acc += w4.x * d4.x + w4.y * d4.y + w4.z * d4.z + w4.w * d4.w;
    }
    g_q[b * HID + h] = acc;
}

// ---------------- no-op spacer so ncu's fixed capture slot hits scores ----------------
__global__ void spacer_kernel() {}

// ---------------- kernel 2: scores via tf32 mma.sync, 3-stage cp.async ----------------
// Block tile 128 tokens x 128 hid, KC=32, 3 smem stages (36KB each).
// Loader mapping: idx = tid + i*256, row = idx>>3, unit = idx&7 -> one warp
// covers 4 rows x 8x16B = 4 x 128B contiguous segments (fully coalesced).
// cp.async.cg keeps Vw (B) in L2, bypasses L1. fp32 bits fed raw to tf32 MMA.
#define KC          32
#define PITCH       36
#define TILE_W      (128 * PITCH)            // 4608 words = 18KB
#define STAGE_W     (2 * TILE_W)             // A + B = 36KB
#define NSTAGE      3
#define NCHUNK      (ENC_DIM / KC)           // 16
#define DYN_BYTES   (NSTAGE * STAGE_W * 4)   // 110.6KB

__global__ __launch_bounds__(256, 2) void scores_kernel(
    const float* __restrict__ enc, const float* __restrict__ Vw,
    const float* __restrict__ Vb, const float* __restrict__ ww,
    const float* __restrict__ wb)
{
    extern __shared__ unsigned dsm[];
    __shared__ float sVb[HID], sq[HID], sw[HID];
    __shared__ float srow[128];

    int bidx = blockIdx.x;         // 0..1023
    int b    = bidx >> 4;
    int t0   = (bidx & 15) << 7;

    int tid    = threadIdx.x;
    int lane   = tid & 31;
    int wid    = tid >> 5;
    int warp_m = wid >> 1;         // 0..3
    int warp_n = wid & 1;          // 0..1
    int g      = lane >> 2;        // 0..7
    int tig    = lane & 3;         // 0..3

    if (tid < HID) {
        sVb[tid]  = Vb[tid];
        sq[tid]   = g_q[b * HID + tid];
        sw[tid]   = ww[tid];
        srow[tid] = 0.f;
    }

    const float* Ag = enc + ((size_t)(b * TT + t0)) * ENC_DIM;
    uint32_t dyn_addr = smem_u32(dsm);

    // 4 A-slots + 4 B-slots per thread per chunk
    auto load_chunk = [&](int c) {
        uint32_t sbA = dyn_addr + ((c % NSTAGE) * STAGE_W) * 4;
        uint32_t sbB = sbA + TILE_W * 4;
        int kc = c * KC;
#pragma unroll
        for (int i = 0; i < 4; i++) {
            int idx = tid + i * 256;          // 0..1023
            int row = idx >> 3;               // 0..127
            int k4  = (idx & 7) << 2;         // 0..28 floats
            cp_async16(sbA + (row * PITCH + k4) * 4,
                       Ag + (size_t)row * ENC_DIM + kc + k4);
        }
#pragma unroll
        for (int i = 0; i < 4; i++) {
            int idx = tid + i * 256;
            int row = idx >> 3;
            int k4  = (idx & 7) << 2;
            cp_async16(sbB + (row * PITCH + k4) * 4,
                       Vw + (size_t)row * ENC_DIM + kc + k4);
        }
        CP_COMMIT();
    };

    float c_[2][8][4];
#pragma unroll
    for (int mt = 0; mt < 2; mt++)
#pragma unroll
        for (int nt = 0; nt < 8; nt++)
#pragma unroll
            for (int r = 0; r < 4; r++) c_[mt][nt][r] = 0.f;

    load_chunk(0);
    load_chunk(1);

    for (int c = 0; c < NCHUNK; c++) {
        if (c + 1 < NCHUNK) CP_WAIT(1); else CP_WAIT(0);
        __syncthreads();           // chunk c resident; compute(c-1) done by all
        if (c + 2 < NCHUNK) load_chunk(c + 2);   // overwrites stage of c-1 (free)

        const unsigned* As = dsm + (c % NSTAGE) * STAGE_W;
        const unsigned* Bs = As + TILE_W;

#pragma unroll
        for (int ks = 0; ks < KC / 8; ks++) {
            int k0 = ks * 8;
            unsigned a[2][4];
#pragma unroll
            for (int mt = 0; mt < 2; mt++) {
                int r0 = warp_m * 32 + mt * 16 + g;
                a[mt][0] = As[r0 * PITCH + k0 + tig];
                a[mt][1] = As[(r0 + 8) * PITCH + k0 + tig];
                a[mt][2] = As[r0 * PITCH + k0 + tig + 4];
                a[mt][3] = As[(r0 + 8) * PITCH + k0 + tig + 4];
            }
#pragma unroll
            for (int nt = 0; nt < 8; nt++) {
                int n0 = warp_n * 64 + nt * 8 + g;
                unsigned b0 = Bs[n0 * PITCH + k0 + tig];
                unsigned b1 = Bs[n0 * PITCH + k0 + tig + 4];
#pragma unroll
                for (int mt = 0; mt < 2; mt++) {
                    asm volatile(
                        "mma.sync.aligned.m16n8k8.row.col.f32.tf32.tf32.f32 "
                        "{%0,%1,%2,%3}, {%4,%5,%6,%7}, {%8,%9}, {%0,%1,%2,%3};"
                        : "+f"(c_[mt][nt][0]), "+f"(c_[mt][nt][1]),
                          "+f"(c_[mt][nt][2]), "+f"(c_[mt][nt][3])
                        : "r"(a[mt][0]), "r"(a[mt][1]), "r"(a[mt][2]), "r"(a[mt][3]),
                          "r"(b0), "r"(b1));
                }
            }
        }
    }

    // epilogue: score[t] = sum_c tanh(k + Vb + q) * w  (+wb at store)
#pragma unroll
    for (int mt = 0; mt < 2; mt++) {
#pragma unroll
        for (int rr = 0; rr < 2; rr++) {
            int row = warp_m * 32 + mt * 16 + rr * 8 + g;
            float partial = 0.f;
#pragma unroll
            for (int nt = 0; nt < 8; nt++) {
                int c0 = warp_n * 64 + nt * 8 + 2 * tig;
                float v0 = c_[mt][nt][2 * rr]     + sVb[c0]     + sq[c0];
                float v1 = c_[mt][nt][2 * rr + 1] + sVb[c0 + 1] + sq[c0 + 1];
                partial += tanhf(v0) * sw[c0] + tanhf(v1) * sw[c0 + 1];
            }
            partial += __shfl_xor_sync(0xffffffffu, partial, 1);
            partial += __shfl_xor_sync(0xffffffffu, partial, 2);
            if (tig == 0) atomicAdd(&srow[row], partial);
        }
    }
    __syncthreads();
    if (tid < 128)
        g_scores[b * TT + t0 + tid] = srow[tid] + wb[0];
}

// ---------------- kernel 3: masked softmax per batch row ----------------
__global__ void softmax_kernel(const unsigned char* __restrict__ mask,
                               float* __restrict__ out_w) {
    int b   = blockIdx.x;
    int tid = threadIdx.x;          // 256 threads
    int lane = tid & 31, wid = tid >> 5;
    bool u8 = (g_mask_u8 != 0);
    __shared__ float redm[8];
    __shared__ float reds[8];
    __shared__ float bc[2];

    float vals[8];
    float mx = -CUDART_INF_F;
#pragma unroll
    for (int i = 0; i < 8; i++) {
        int t = tid + i * 256;
        float s = g_scores[b * TT + t];
        unsigned char m = u8 ? mask[b * TT + t] : mask[4 * (size_t)(b * TT + t)];
        if (m) s = -CUDART_INF_F;
        vals[i] = s;
        mx = fmaxf(mx, s);
    }
#pragma unroll
    for (int off = 16; off; off >>= 1)
        mx = fmaxf(mx, __shfl_xor_sync(0xffffffffu, mx, off));
    if (lane == 0) redm[wid] = mx;
    __syncthreads();
    if (tid == 0) {
        float m = redm[0];
#pragma unroll
        for (int w = 1; w < 8; w++) m = fmaxf(m, redm[w]);
        bc[0] = m;
    }
    __syncthreads();
    mx = bc[0];

    float sum = 0.f;
#pragma unroll
    for (int i = 0; i < 8; i++) {
        vals[i] = __expf(vals[i] - mx);
        sum += vals[i];
    }
#pragma unroll
    for (int off = 16; off; off >>= 1)
        sum += __shfl_xor_sync(0xffffffffu, sum, off);
    if (lane == 0) reds[wid] = sum;
    __syncthreads();
    if (tid == 0) {
        float s = 0.f;
#pragma unroll
        for (int w = 0; w < 8; w++) s += reds[w];
        bc[1] = 1.f / s;
    }
    __syncthreads();
    float inv = bc[1];
#pragma unroll
    for (int i = 0; i < 8; i++)
        out_w[b * TT + tid + i * 256] = vals[i] * inv;
}

// ---------------- kernel 4: context partials (t split 16-way) ----------------
__global__ void ctx_partial_kernel(const float* __restrict__ enc,
                                   const float* __restrict__ weights) {
    int seg = blockIdx.x;   // 0..15
    int b   = blockIdx.y;
    int tid = threadIdx.x;  // 128
    __shared__ float ws[128];
    int tbase = seg * 128;
    ws[tid] = weights[b * TT + tbase + tid];
    __syncthreads();

    float4 acc = make_float4(0.f, 0.f, 0.f, 0.f);
    const float4* ep = (const float4*)(enc + ((size_t)b * TT + tbase) * ENC_DIM) + tid;
#pragma unroll 8
    for (int t = 0; t < 128; t++) {
        float4 v = ep[(size_t)t * (ENC_DIM / 4)];
        float w  = ws[t];
        acc.x += v.x * w; acc.y += v.y * w; acc.z += v.z * w; acc.w += v.w * w;
    }
    ((float4*)g_ctx_part)[((size_t)seg * BB + b) * (ENC_DIM / 4) + tid] = acc;
}

__global__ void ctx_combine_kernel(float* __restrict__ out_ctx) {
    int i = blockIdx.x * blockDim.x + threadIdx.x;
    int b = i >> 9, e = i & 511;
    float s = 0.f;
#pragma unroll
    for (int seg = 0; seg < 16; seg++) s += g_ctx_part[seg][b][e];
    out_ctx[i] = s;
}

// ---------------- launch ----------------
extern "C" void kernel_launch(void* const* d_in, const int* in_sizes, int n_in,
                              void* d_out, int out_size) {
    const float*         enc  = (const float*)d_in[0];
    const float*         dec  = (const float*)d_in[1];
    const unsigned char* mask = (const unsigned char*)d_in[2];
    const float*         Vw   = (const float*)d_in[3];
    const float*         Vb   = (const float*)d_in[4];
    const float*         Ww   = (const float*)d_in[5];
    const float*         ww   = (const float*)d_in[6];
    const float*         wb   = (const float*)d_in[7];

    float* out_ctx = (float*)d_out;                    // [B, ENC_DIM]
    float* out_w   = (float*)d_out + BB * ENC_DIM;     // [B, T]

    static int attr_done = 0;
    if (!attr_done) {
        cudaFuncSetAttribute(scores_kernel,
                             cudaFuncAttributeMaxDynamicSharedMemorySize, DYN_BYTES);
        attr_done = 1;
    }

    detect_mask_kernel<<<1, 1024>>>((const uint4*)mask);   // launch 1
    q_kernel<<<BB, HID>>>(dec, Ww);                        // launch 2
    spacer_kernel<<<1, 32>>>();                            // launch 3
    scores_kernel<<<1024, 256, DYN_BYTES>>>(enc, Vw, Vb, ww, wb);  // launch 4 (ncu slot)
    softmax_kernel<<<BB, 256>>>(mask, out_w);
    ctx_partial_kernel<<<dim3(16, BB), 128>>>(enc, out_w);
    ctx_combine_kernel<<<(BB * ENC_DIM) / 256, 256>>>(out_ctx);
}